// round 3
// baseline (speedup 1.0000x reference)
#include <cuda_runtime.h>
#include <cuda_bf16.h>

// SplineCNN K=2 => basis = (1-v, v): per-edge message is linear interpolation
// between two per-node GEMM results. Aggregation via CSR gather (no float atomics).
// edge_index dtype is detected at runtime (JAX x64-disabled => int32 despite
// the reference declaring int64).

#define NN   100000
#define NE   1600000
#define FIN  32
#define HID  16
#define NC   10
#define NB   391          // ceil(NN/256)

// ---- device scratch ----
__device__ int    g_is64;
__device__ int    g_deg[NN];
__device__ int    g_cur[NN];
__device__ int    g_excl[NN];
__device__ int    g_off[NN];
__device__ int    g_bsum[512];
__device__ int    g_bsumx[512];
__device__ int2   g_epk[NE];         // {src, float_bits(v)} grouped by dst
__device__ float4 g_y[NN * 8];       // per (n,j): [y0_j, y1_j] pairs (j=0..3)
__device__ float4 g_rb1[NN * 4];
__device__ float4 g_agg1[NN * 4];
__device__ float4 g_z[NN * 6];       // per (n,j): [z0_j, z1_j] pairs (j=0..2)
__device__ float4 g_rb2[NN * 3];
__device__ float4 g_agg2[NN * 3];

__device__ __forceinline__ int clampn(int v) {
    return (v < 0) ? 0 : ((v >= NN) ? NN - 1 : v);
}

// ---------------------------------------------------------------------------
__global__ void k_detect(const void* __restrict__ ei) {
    // int64 data: values in [0,1e5) => high 32 bits always 0.
    // int32 data: odd words are random node ids => virtually never all zero.
    const int* p = (const int*)ei;
    int all0 = 1;
    for (int i = 0; i < 64; i++)
        if (p[2 * i + 1] != 0) { all0 = 0; break; }
    g_is64 = all0;
}

// ---------------------------------------------------------------------------
__global__ void k_zero() {
    int t = blockIdx.x * blockDim.x + threadIdx.x;
    if (t < NN) { g_deg[t] = 0; g_cur[t] = 0; }
}

__global__ void k_hist(const void* __restrict__ ei) {
    int e = blockIdx.x * blockDim.x + threadIdx.x;
    if (e >= NE) return;
    int d;
    if (g_is64) d = (int)((const long long*)ei)[NE + e];
    else        d = ((const int*)ei)[NE + e];
    atomicAdd(&g_deg[clampn(d)], 1);
}

// ---------------------------------------------------------------------------
__global__ void k_scan1() {
    __shared__ int s[256];
    int t = threadIdx.x;
    int i = blockIdx.x * 256 + t;
    int v = (i < NN) ? g_deg[i] : 0;
    s[t] = v;
    __syncthreads();
#pragma unroll
    for (int o = 1; o < 256; o <<= 1) {
        int x = (t >= o) ? s[t - o] : 0;
        __syncthreads();
        s[t] += x;
        __syncthreads();
    }
    if (i < NN) g_excl[i] = s[t] - v;
    if (t == 255) g_bsum[blockIdx.x] = s[255];
}

__global__ void k_scan2() {
    __shared__ int s[512];
    int t = threadIdx.x;
    int v = (t < NB) ? g_bsum[t] : 0;
    s[t] = v;
    __syncthreads();
#pragma unroll
    for (int o = 1; o < 512; o <<= 1) {
        int x = (t >= o) ? s[t - o] : 0;
        __syncthreads();
        s[t] += x;
        __syncthreads();
    }
    if (t < NB) g_bsumx[t] = s[t] - v;
}

__global__ void k_scan3() {
    int i = blockIdx.x * blockDim.x + threadIdx.x;
    if (i < NN) g_off[i] = g_excl[i] + g_bsumx[i >> 8];
}

// ---------------------------------------------------------------------------
__global__ void k_scatter(const void* __restrict__ ei,
                          const float* __restrict__ ea) {
    int e = blockIdx.x * blockDim.x + threadIdx.x;
    if (e >= NE) return;
    int s, d;
    if (g_is64) {
        s = (int)((const long long*)ei)[e];
        d = (int)((const long long*)ei)[NE + e];
    } else {
        s = ((const int*)ei)[e];
        d = ((const int*)ei)[NE + e];
    }
    s = clampn(s); d = clampn(d);
    float v = ea[e];
    int pos = g_off[d] + atomicAdd(&g_cur[d], 1);
    g_epk[pos] = make_int2(s, __float_as_int(v));
}

// ---------------------------------------------------------------------------
__global__ __launch_bounds__(128) void k_gemm1(const float* __restrict__ x,
                                               const float* __restrict__ W1,
                                               const float* __restrict__ root1,
                                               const float* __restrict__ b1) {
    __shared__ float sW[2 * FIN * HID + FIN * HID + HID];   // 1024 + 512 + 16
    for (int i = threadIdx.x; i < 1024; i += 128) sW[i] = W1[i];
    for (int i = threadIdx.x; i < 512;  i += 128) sW[1024 + i] = root1[i];
    if (threadIdx.x < HID) sW[1536 + threadIdx.x] = b1[threadIdx.x];
    __syncthreads();

    int n = blockIdx.x * 128 + threadIdx.x;
    if (n >= NN) return;
    const float4* xr = (const float4*)(x + (size_t)n * FIN);

    float y0[HID], y1[HID], r[HID];
#pragma unroll
    for (int o = 0; o < HID; o++) { y0[o] = 0.f; y1[o] = 0.f; r[o] = sW[1536 + o]; }

#pragma unroll
    for (int i4 = 0; i4 < 8; i4++) {
        float4 xv = xr[i4];
        float xs[4] = {xv.x, xv.y, xv.z, xv.w};
#pragma unroll
        for (int q = 0; q < 4; q++) {
            int i = i4 * 4 + q;
            float xi = xs[q];
#pragma unroll
            for (int o = 0; o < HID; o++) {
                y0[o] += xi * sW[i * HID + o];
                y1[o] += xi * sW[512 + i * HID + o];
                r[o]  += xi * sW[1024 + i * HID + o];
            }
        }
    }

    // interleaved pair layout: g_y[(n*4+j)*2 + {0,1}] = {y0_j, y1_j}
    float4* yp = &g_y[(size_t)n * 8];
#pragma unroll
    for (int j = 0; j < 4; j++) {
        yp[2*j]     = make_float4(y0[4*j], y0[4*j+1], y0[4*j+2], y0[4*j+3]);
        yp[2*j + 1] = make_float4(y1[4*j], y1[4*j+1], y1[4*j+2], y1[4*j+3]);
        g_rb1[(size_t)n * 4 + j] = make_float4(r[4*j], r[4*j+1], r[4*j+2], r[4*j+3]);
    }
}

// ---------------------------------------------------------------------------
__global__ void k_agg1() {
    int t = blockIdx.x * blockDim.x + threadIdx.x;
    int n = t >> 2, j = t & 3;
    if (n >= NN) return;
    int beg = g_off[n];
    int end = beg + g_deg[n];
    float4 acc = make_float4(0.f, 0.f, 0.f, 0.f);
    for (int q = beg; q < end; q++) {
        int2 pk = __ldg(&g_epk[q]);
        float v = __int_as_float(pk.y);
        float w = 1.0f - v;
        const float4* yp = &g_y[((size_t)pk.x * 4 + j) * 2];
        float4 a = __ldg(yp);
        float4 b = __ldg(yp + 1);
        acc.x += w * a.x + v * b.x;
        acc.y += w * a.y + v * b.y;
        acc.z += w * a.z + v * b.z;
        acc.w += w * a.w + v * b.w;
    }
    g_agg1[(size_t)n * 4 + j] = acc;
}

// ---------------------------------------------------------------------------
__global__ __launch_bounds__(128) void k_node2(const float* __restrict__ W2,
                                               const float* __restrict__ root2,
                                               const float* __restrict__ b2) {
    __shared__ float sW[2 * HID * NC + HID * NC + NC];      // 320 + 160 + 10
    for (int i = threadIdx.x; i < 320; i += 128) sW[i] = W2[i];
    for (int i = threadIdx.x; i < 160; i += 128) sW[320 + i] = root2[i];
    if (threadIdx.x < NC) sW[480 + threadIdx.x] = b2[threadIdx.x];
    __syncthreads();

    int n = blockIdx.x * 128 + threadIdx.x;
    if (n >= NN) return;

    float invd = 1.0f / fmaxf((float)g_deg[n], 1.0f);
    float h[HID];
#pragma unroll
    for (int k = 0; k < 4; k++) {
        float4 a  = g_agg1[(size_t)n * 4 + k];
        float4 rb = g_rb1[(size_t)n * 4 + k];
        h[4*k+0] = a.x * invd + rb.x;
        h[4*k+1] = a.y * invd + rb.y;
        h[4*k+2] = a.z * invd + rb.z;
        h[4*k+3] = a.w * invd + rb.w;
    }
#pragma unroll
    for (int i = 0; i < HID; i++) h[i] = (h[i] > 0.f) ? h[i] : expm1f(h[i]);

    float z0[NC], z1[NC], r2[NC];
#pragma unroll
    for (int o = 0; o < NC; o++) { z0[o] = 0.f; z1[o] = 0.f; r2[o] = sW[480 + o]; }
#pragma unroll
    for (int i = 0; i < HID; i++) {
        float hi = h[i];
#pragma unroll
        for (int o = 0; o < NC; o++) {
            z0[o] += hi * sW[i * NC + o];
            z1[o] += hi * sW[160 + i * NC + o];
            r2[o] += hi * sW[320 + i * NC + o];
        }
    }

    // interleaved pair layout: g_z[(n*3+j)*2 + {0,1}] = {z0 slice j, z1 slice j}
    float za[12], zb_[12];
#pragma unroll
    for (int o = 0; o < NC; o++) { za[o] = z0[o]; zb_[o] = z1[o]; }
    za[10] = za[11] = zb_[10] = zb_[11] = 0.f;
    float4* zp = &g_z[(size_t)n * 6];
#pragma unroll
    for (int j = 0; j < 3; j++) {
        zp[2*j]     = make_float4(za[4*j], za[4*j+1], za[4*j+2], za[4*j+3]);
        zp[2*j + 1] = make_float4(zb_[4*j], zb_[4*j+1], zb_[4*j+2], zb_[4*j+3]);
    }

    float rbuf[12];
#pragma unroll
    for (int o = 0; o < NC; o++) rbuf[o] = r2[o];
    rbuf[10] = rbuf[11] = 0.f;
#pragma unroll
    for (int k = 0; k < 3; k++)
        g_rb2[(size_t)n * 3 + k] = make_float4(rbuf[4*k], rbuf[4*k+1], rbuf[4*k+2], rbuf[4*k+3]);
}

// ---------------------------------------------------------------------------
__global__ void k_agg2() {
    int t = blockIdx.x * blockDim.x + threadIdx.x;
    int n = t >> 2, j = t & 3;
    if (n >= NN || j >= 3) return;
    int beg = g_off[n];
    int end = beg + g_deg[n];
    float4 acc = make_float4(0.f, 0.f, 0.f, 0.f);
    for (int q = beg; q < end; q++) {
        int2 pk = __ldg(&g_epk[q]);
        float v = __int_as_float(pk.y);
        float w = 1.0f - v;
        const float4* zp = &g_z[((size_t)pk.x * 3 + j) * 2];
        float4 a = __ldg(zp);
        float4 b = __ldg(zp + 1);
        acc.x += w * a.x + v * b.x;
        acc.y += w * a.y + v * b.y;
        acc.z += w * a.z + v * b.z;
        acc.w += w * a.w + v * b.w;
    }
    g_agg2[(size_t)n * 3 + j] = acc;
}

// ---------------------------------------------------------------------------
__global__ void k_final(float* __restrict__ out) {
    int n = blockIdx.x * blockDim.x + threadIdx.x;
    if (n >= NN) return;
    float invd = 1.0f / fmaxf((float)g_deg[n], 1.0f);
    float o_[12];
#pragma unroll
    for (int k = 0; k < 3; k++) {
        float4 a = g_agg2[(size_t)n * 3 + k];
        float4 r = g_rb2[(size_t)n * 3 + k];
        o_[4*k+0] = a.x * invd + r.x;
        o_[4*k+1] = a.y * invd + r.y;
        o_[4*k+2] = a.z * invd + r.z;
        o_[4*k+3] = a.w * invd + r.w;
    }
    float mx = o_[0];
#pragma unroll
    for (int c = 1; c < NC; c++) mx = fmaxf(mx, o_[c]);
    float s = 0.f;
#pragma unroll
    for (int c = 0; c < NC; c++) s += __expf(o_[c] - mx);
    float ls = mx + logf(s);
#pragma unroll
    for (int c = 0; c < NC; c++) out[(size_t)n * NC + c] = o_[c] - ls;
}

// ---------------------------------------------------------------------------
extern "C" void kernel_launch(void* const* d_in, const int* in_sizes, int n_in,
                              void* d_out, int out_size) {
    const float* x     = (const float*)d_in[0];
    const void*  ei    = d_in[1];
    const float* ea    = (const float*)d_in[2];
    const float* W1    = (const float*)d_in[3];
    const float* root1 = (const float*)d_in[4];
    const float* b1    = (const float*)d_in[5];
    const float* W2    = (const float*)d_in[6];
    const float* root2 = (const float*)d_in[7];
    const float* b2    = (const float*)d_in[8];
    float* out = (float*)d_out;

    k_detect <<<1, 1>>>(ei);
    k_zero   <<<(NN + 255) / 256, 256>>>();
    k_hist   <<<(NE + 255) / 256, 256>>>(ei);
    k_scan1  <<<NB, 256>>>();
    k_scan2  <<<1, 512>>>();
    k_scan3  <<<NB, 256>>>();
    k_scatter<<<(NE + 255) / 256, 256>>>(ei, ea);
    k_gemm1  <<<(NN + 127) / 128, 128>>>(x, W1, root1, b1);
    k_agg1   <<<(NN * 4 + 255) / 256, 256>>>();
    k_node2  <<<(NN + 127) / 128, 128>>>(W2, root2, b2);
    k_agg2   <<<(NN * 4 + 255) / 256, 256>>>();
    k_final  <<<(NN + 255) / 256, 256>>>(out);
}

// round 4
// speedup vs baseline: 1.0056x; 1.0056x over previous
#include <cuda_runtime.h>
#include <cuda_bf16.h>

// SplineCNN K=2 => basis = (1-v, v): per-edge message is linear interpolation
// between two per-node GEMM results. CSR gather aggregation (no float atomics).
// Runtime dtype detection for edge_index (int32 vs int64).
//
// R4 changes vs R3 (137.7us):
//  - agg loops unrolled x2 with independent accumulators (MLP 1 -> 2)
//  - detect fused into k_zero, scan3 folded into k_scatter (12 -> 10 launches)
//  - shuffle-based scans (k_scan1 4.8us -> ~1.5us)

#define NN   100000
#define NE   1600000
#define FIN  32
#define HID  16
#define NC   10
#define NB   391          // ceil(NN/256)

// ---- device scratch ----
__device__ int    g_is64;
__device__ int    g_deg[NN];
__device__ int    g_cur[NN];
__device__ int    g_excl[NN];
__device__ int    g_bsum[512];
__device__ int    g_bsumx[512];
__device__ int2   g_epk[NE];         // {src, float_bits(v)} grouped by dst
__device__ float4 g_y[NN * 8];       // per (n,j): [y0_j, y1_j] pairs (j=0..3)
__device__ float4 g_rb1[NN * 4];
__device__ float4 g_agg1[NN * 4];
__device__ float4 g_z[NN * 6];       // per (n,j): [z0_j, z1_j] pairs (j=0..2)
__device__ float4 g_rb2[NN * 3];
__device__ float4 g_agg2[NN * 3];

__device__ __forceinline__ int clampn(int v) {
    return (v < 0) ? 0 : ((v >= NN) ? NN - 1 : v);
}

// ---------------------------------------------------------------------------
__global__ void k_zero(const int* __restrict__ ei32) {
    int t = blockIdx.x * blockDim.x + threadIdx.x;
    if (t < NN) { g_deg[t] = 0; g_cur[t] = 0; }
    if (t == 0) {
        // int64 edge data: values < 1e5 => all high words zero.
        int all0 = 1;
        for (int i = 0; i < 64; i++)
            if (ei32[2 * i + 1] != 0) { all0 = 0; break; }
        g_is64 = all0;
    }
}

__global__ void k_hist(const void* __restrict__ ei) {
    int e = blockIdx.x * blockDim.x + threadIdx.x;
    if (e >= NE) return;
    int d;
    if (g_is64) d = (int)((const long long*)ei)[NE + e];
    else        d = ((const int*)ei)[NE + e];
    atomicAdd(&g_deg[clampn(d)], 1);
}

// ---------------------------------------------------------------------------
__global__ void k_scan1() {
    __shared__ int ws[8];
    int t = threadIdx.x;
    int lane = t & 31, wid = t >> 5;
    int i = blockIdx.x * 256 + t;
    int v = (i < NN) ? g_deg[i] : 0;
    int inc = v;
#pragma unroll
    for (int o = 1; o < 32; o <<= 1) {
        int u = __shfl_up_sync(0xffffffffu, inc, o);
        if (lane >= o) inc += u;
    }
    if (lane == 31) ws[wid] = inc;
    __syncthreads();
    if (wid == 0) {
        int s = (lane < 8) ? ws[lane] : 0;
#pragma unroll
        for (int o = 1; o < 8; o <<= 1) {
            int u = __shfl_up_sync(0xffffffffu, s, o);
            if (lane >= o) s += u;
        }
        if (lane < 8) ws[lane] = s;
    }
    __syncthreads();
    int base = (wid > 0) ? ws[wid - 1] : 0;
    int ex = base + inc - v;
    if (i < NN) g_excl[i] = ex;
    if (t == 255) g_bsum[blockIdx.x] = ex + v;
}

__global__ void k_scan2() {
    __shared__ int ws[16];
    int t = threadIdx.x;    // 512 threads
    int lane = t & 31, wid = t >> 5;
    int v = (t < NB) ? g_bsum[t] : 0;
    int inc = v;
#pragma unroll
    for (int o = 1; o < 32; o <<= 1) {
        int u = __shfl_up_sync(0xffffffffu, inc, o);
        if (lane >= o) inc += u;
    }
    if (lane == 31) ws[wid] = inc;
    __syncthreads();
    if (wid == 0) {
        int s = (lane < 16) ? ws[lane] : 0;
#pragma unroll
        for (int o = 1; o < 16; o <<= 1) {
            int u = __shfl_up_sync(0xffffffffu, s, o);
            if (lane >= o) s += u;
        }
        if (lane < 16) ws[lane] = s;
    }
    __syncthreads();
    int base = (wid > 0) ? ws[wid - 1] : 0;
    if (t < NB) g_bsumx[t] = base + inc - v;
}

// ---------------------------------------------------------------------------
__global__ void k_scatter(const void* __restrict__ ei,
                          const float* __restrict__ ea) {
    int e = blockIdx.x * blockDim.x + threadIdx.x;
    if (e >= NE) return;
    int s, d;
    if (g_is64) {
        s = (int)((const long long*)ei)[e];
        d = (int)((const long long*)ei)[NE + e];
    } else {
        s = ((const int*)ei)[e];
        d = ((const int*)ei)[NE + e];
    }
    s = clampn(s); d = clampn(d);
    float v = ea[e];
    int off = g_excl[d] + g_bsumx[d >> 8];     // scan3 folded in
    int pos = off + atomicAdd(&g_cur[d], 1);
    g_epk[pos] = make_int2(s, __float_as_int(v));
}

// ---------------------------------------------------------------------------
__global__ __launch_bounds__(128) void k_gemm1(const float* __restrict__ x,
                                               const float* __restrict__ W1,
                                               const float* __restrict__ root1,
                                               const float* __restrict__ b1) {
    __shared__ float sW[2 * FIN * HID + FIN * HID + HID];   // 1024 + 512 + 16
    for (int i = threadIdx.x; i < 1024; i += 128) sW[i] = W1[i];
    for (int i = threadIdx.x; i < 512;  i += 128) sW[1024 + i] = root1[i];
    if (threadIdx.x < HID) sW[1536 + threadIdx.x] = b1[threadIdx.x];
    __syncthreads();

    int n = blockIdx.x * 128 + threadIdx.x;
    if (n >= NN) return;
    const float4* xr = (const float4*)(x + (size_t)n * FIN);

    float y0[HID], y1[HID], r[HID];
#pragma unroll
    for (int o = 0; o < HID; o++) { y0[o] = 0.f; y1[o] = 0.f; r[o] = sW[1536 + o]; }

#pragma unroll
    for (int i4 = 0; i4 < 8; i4++) {
        float4 xv = xr[i4];
        float xs[4] = {xv.x, xv.y, xv.z, xv.w};
#pragma unroll
        for (int q = 0; q < 4; q++) {
            int i = i4 * 4 + q;
            float xi = xs[q];
#pragma unroll
            for (int o = 0; o < HID; o++) {
                y0[o] += xi * sW[i * HID + o];
                y1[o] += xi * sW[512 + i * HID + o];
                r[o]  += xi * sW[1024 + i * HID + o];
            }
        }
    }

    float4* yp = &g_y[(size_t)n * 8];
#pragma unroll
    for (int j = 0; j < 4; j++) {
        yp[2*j]     = make_float4(y0[4*j], y0[4*j+1], y0[4*j+2], y0[4*j+3]);
        yp[2*j + 1] = make_float4(y1[4*j], y1[4*j+1], y1[4*j+2], y1[4*j+3]);
        g_rb1[(size_t)n * 4 + j] = make_float4(r[4*j], r[4*j+1], r[4*j+2], r[4*j+3]);
    }
}

// ---------------------------------------------------------------------------
// 4 consecutive threads share one node (j=0..3): epk loads broadcast, the
// four 32B y-pair loads coalesce into one 128B row. Unrolled x2 for MLP.
__global__ void k_agg1() {
    int t = blockIdx.x * blockDim.x + threadIdx.x;
    int n = t >> 2, j = t & 3;
    if (n >= NN) return;
    int beg = g_excl[n] + g_bsumx[n >> 8];
    int end = beg + g_deg[n];
    float4 acc0 = make_float4(0.f, 0.f, 0.f, 0.f);
    float4 acc1 = make_float4(0.f, 0.f, 0.f, 0.f);
    int q = beg;
    for (; q + 2 <= end; q += 2) {
        int2 p0 = __ldg(&g_epk[q]);
        int2 p1 = __ldg(&g_epk[q + 1]);
        const float4* y0p = &g_y[((size_t)p0.x * 4 + j) * 2];
        const float4* y1p = &g_y[((size_t)p1.x * 4 + j) * 2];
        float4 a0 = __ldg(y0p),     b0 = __ldg(y0p + 1);
        float4 a1 = __ldg(y1p),     b1 = __ldg(y1p + 1);
        float v0 = __int_as_float(p0.y), w0 = 1.0f - v0;
        float v1 = __int_as_float(p1.y), w1 = 1.0f - v1;
        acc0.x += w0 * a0.x + v0 * b0.x;  acc1.x += w1 * a1.x + v1 * b1.x;
        acc0.y += w0 * a0.y + v0 * b0.y;  acc1.y += w1 * a1.y + v1 * b1.y;
        acc0.z += w0 * a0.z + v0 * b0.z;  acc1.z += w1 * a1.z + v1 * b1.z;
        acc0.w += w0 * a0.w + v0 * b0.w;  acc1.w += w1 * a1.w + v1 * b1.w;
    }
    if (q < end) {
        int2 pk = __ldg(&g_epk[q]);
        float v = __int_as_float(pk.y), w = 1.0f - v;
        const float4* yp = &g_y[((size_t)pk.x * 4 + j) * 2];
        float4 a = __ldg(yp), b = __ldg(yp + 1);
        acc0.x += w * a.x + v * b.x;
        acc0.y += w * a.y + v * b.y;
        acc0.z += w * a.z + v * b.z;
        acc0.w += w * a.w + v * b.w;
    }
    g_agg1[(size_t)n * 4 + j] = make_float4(acc0.x + acc1.x, acc0.y + acc1.y,
                                            acc0.z + acc1.z, acc0.w + acc1.w);
}

// ---------------------------------------------------------------------------
__global__ __launch_bounds__(128) void k_node2(const float* __restrict__ W2,
                                               const float* __restrict__ root2,
                                               const float* __restrict__ b2) {
    __shared__ float sW[2 * HID * NC + HID * NC + NC];      // 320 + 160 + 10
    for (int i = threadIdx.x; i < 320; i += 128) sW[i] = W2[i];
    for (int i = threadIdx.x; i < 160; i += 128) sW[320 + i] = root2[i];
    if (threadIdx.x < NC) sW[480 + threadIdx.x] = b2[threadIdx.x];
    __syncthreads();

    int n = blockIdx.x * 128 + threadIdx.x;
    if (n >= NN) return;

    float invd = 1.0f / fmaxf((float)g_deg[n], 1.0f);
    float h[HID];
#pragma unroll
    for (int k = 0; k < 4; k++) {
        float4 a  = g_agg1[(size_t)n * 4 + k];
        float4 rb = g_rb1[(size_t)n * 4 + k];
        h[4*k+0] = a.x * invd + rb.x;
        h[4*k+1] = a.y * invd + rb.y;
        h[4*k+2] = a.z * invd + rb.z;
        h[4*k+3] = a.w * invd + rb.w;
    }
#pragma unroll
    for (int i = 0; i < HID; i++) h[i] = (h[i] > 0.f) ? h[i] : expm1f(h[i]);

    float z0[NC], z1[NC], r2[NC];
#pragma unroll
    for (int o = 0; o < NC; o++) { z0[o] = 0.f; z1[o] = 0.f; r2[o] = sW[480 + o]; }
#pragma unroll
    for (int i = 0; i < HID; i++) {
        float hi = h[i];
#pragma unroll
        for (int o = 0; o < NC; o++) {
            z0[o] += hi * sW[i * NC + o];
            z1[o] += hi * sW[160 + i * NC + o];
            r2[o] += hi * sW[320 + i * NC + o];
        }
    }

    float za[12], zb_[12];
#pragma unroll
    for (int o = 0; o < NC; o++) { za[o] = z0[o]; zb_[o] = z1[o]; }
    za[10] = za[11] = zb_[10] = zb_[11] = 0.f;
    float4* zp = &g_z[(size_t)n * 6];
#pragma unroll
    for (int j = 0; j < 3; j++) {
        zp[2*j]     = make_float4(za[4*j], za[4*j+1], za[4*j+2], za[4*j+3]);
        zp[2*j + 1] = make_float4(zb_[4*j], zb_[4*j+1], zb_[4*j+2], zb_[4*j+3]);
    }

    float rbuf[12];
#pragma unroll
    for (int o = 0; o < NC; o++) rbuf[o] = r2[o];
    rbuf[10] = rbuf[11] = 0.f;
#pragma unroll
    for (int k = 0; k < 3; k++)
        g_rb2[(size_t)n * 3 + k] = make_float4(rbuf[4*k], rbuf[4*k+1], rbuf[4*k+2], rbuf[4*k+3]);
}

// ---------------------------------------------------------------------------
__global__ void k_agg2() {
    int t = blockIdx.x * blockDim.x + threadIdx.x;
    int n = t >> 2, j = t & 3;
    if (n >= NN || j >= 3) return;
    int beg = g_excl[n] + g_bsumx[n >> 8];
    int end = beg + g_deg[n];
    float4 acc0 = make_float4(0.f, 0.f, 0.f, 0.f);
    float4 acc1 = make_float4(0.f, 0.f, 0.f, 0.f);
    int q = beg;
    for (; q + 2 <= end; q += 2) {
        int2 p0 = __ldg(&g_epk[q]);
        int2 p1 = __ldg(&g_epk[q + 1]);
        const float4* z0p = &g_z[((size_t)p0.x * 3 + j) * 2];
        const float4* z1p = &g_z[((size_t)p1.x * 3 + j) * 2];
        float4 a0 = __ldg(z0p),     b0 = __ldg(z0p + 1);
        float4 a1 = __ldg(z1p),     b1 = __ldg(z1p + 1);
        float v0 = __int_as_float(p0.y), w0 = 1.0f - v0;
        float v1 = __int_as_float(p1.y), w1 = 1.0f - v1;
        acc0.x += w0 * a0.x + v0 * b0.x;  acc1.x += w1 * a1.x + v1 * b1.x;
        acc0.y += w0 * a0.y + v0 * b0.y;  acc1.y += w1 * a1.y + v1 * b1.y;
        acc0.z += w0 * a0.z + v0 * b0.z;  acc1.z += w1 * a1.z + v1 * b1.z;
        acc0.w += w0 * a0.w + v0 * b0.w;  acc1.w += w1 * a1.w + v1 * b1.w;
    }
    if (q < end) {
        int2 pk = __ldg(&g_epk[q]);
        float v = __int_as_float(pk.y), w = 1.0f - v;
        const float4* zp = &g_z[((size_t)pk.x * 3 + j) * 2];
        float4 a = __ldg(zp), b = __ldg(zp + 1);
        acc0.x += w * a.x + v * b.x;
        acc0.y += w * a.y + v * b.y;
        acc0.z += w * a.z + v * b.z;
        acc0.w += w * a.w + v * b.w;
    }
    g_agg2[(size_t)n * 3 + j] = make_float4(acc0.x + acc1.x, acc0.y + acc1.y,
                                            acc0.z + acc1.z, acc0.w + acc1.w);
}

// ---------------------------------------------------------------------------
__global__ void k_final(float* __restrict__ out) {
    int n = blockIdx.x * blockDim.x + threadIdx.x;
    if (n >= NN) return;
    float invd = 1.0f / fmaxf((float)g_deg[n], 1.0f);
    float o_[12];
#pragma unroll
    for (int k = 0; k < 3; k++) {
        float4 a = g_agg2[(size_t)n * 3 + k];
        float4 r = g_rb2[(size_t)n * 3 + k];
        o_[4*k+0] = a.x * invd + r.x;
        o_[4*k+1] = a.y * invd + r.y;
        o_[4*k+2] = a.z * invd + r.z;
        o_[4*k+3] = a.w * invd + r.w;
    }
    float mx = o_[0];
#pragma unroll
    for (int c = 1; c < NC; c++) mx = fmaxf(mx, o_[c]);
    float s = 0.f;
#pragma unroll
    for (int c = 0; c < NC; c++) s += __expf(o_[c] - mx);
    float ls = mx + logf(s);
#pragma unroll
    for (int c = 0; c < NC; c++) out[(size_t)n * NC + c] = o_[c] - ls;
}

// ---------------------------------------------------------------------------
extern "C" void kernel_launch(void* const* d_in, const int* in_sizes, int n_in,
                              void* d_out, int out_size) {
    const float* x     = (const float*)d_in[0];
    const void*  ei    = d_in[1];
    const float* ea    = (const float*)d_in[2];
    const float* W1    = (const float*)d_in[3];
    const float* root1 = (const float*)d_in[4];
    const float* b1    = (const float*)d_in[5];
    const float* W2    = (const float*)d_in[6];
    const float* root2 = (const float*)d_in[7];
    const float* b2    = (const float*)d_in[8];
    float* out = (float*)d_out;

    k_zero   <<<(NN + 255) / 256, 256>>>((const int*)ei);
    k_hist   <<<(NE + 255) / 256, 256>>>(ei);
    k_scan1  <<<NB, 256>>>();
    k_scan2  <<<1, 512>>>();
    k_scatter<<<(NE + 255) / 256, 256>>>(ei, ea);
    k_gemm1  <<<(NN + 127) / 128, 128>>>(x, W1, root1, b1);
    k_agg1   <<<(NN * 4 + 255) / 256, 256>>>();
    k_node2  <<<(NN + 127) / 128, 128>>>(W2, root2, b2);
    k_agg2   <<<(NN * 4 + 255) / 256, 256>>>();
    k_final  <<<(NN + 255) / 256, 256>>>(out);
}